// round 1
// baseline (speedup 1.0000x reference)
#include <cuda_runtime.h>
#include <math.h>

#define SEQ 2048
#define NH 16
#define DQK 192

// ---------------- scratch (no allocations allowed) ----------------
__device__ __align__(16) float g_q1[SEQ * 1536];
__device__ __align__(16) float g_q [SEQ * 3072];
__device__ __align__(16) float g_ckv[SEQ * 512];
__device__ __align__(16) float g_k [SEQ * 3072];
__device__ __align__(16) float g_v [SEQ * 2048];
__device__ __align__(16) float g_p [(size_t)NH * SEQ * SEQ];   // scores / probs
__device__ __align__(16) float g_attn[SEQ * 2048];

// ---------------- generic fp32 tiled GEMM ----------------
// C[m,n] = scale * sum_k A[m,k] * (TRANSB ? B[n,k] : B[k,n])  (+ mask[m*SEQ+n])
// BM=BN=64, BK=16, 256 threads, 4x4 micro-tile. All dims assumed divisible.
template <bool TRANSB, bool MASKED>
__global__ __launch_bounds__(256) void gemm_tile(
    const float* __restrict__ A, const float* __restrict__ B,
    float* __restrict__ C, const float* __restrict__ Msk,
    int K, int lda, int ldb, int ldc,
    long sa, long sb, long sc, float scale)
{
    constexpr int BM = 64, BN = 64, BK = 16;
    __shared__ __align__(16) float As[BK][BM];
    __shared__ __align__(16) float Bs[BK][BN];

    const int tid = threadIdx.x;
    const int tx = tid & 15;     // 0..15  -> 4 output cols each
    const int ty = tid >> 4;     // 0..15  -> 4 output rows each
    const int m0 = blockIdx.y * BM;
    const int n0 = blockIdx.x * BN;

    A += (size_t)blockIdx.z * sa;
    B += (size_t)blockIdx.z * sb;
    C += (size_t)blockIdx.z * sc;

    float acc[4][4] = {};

    for (int kt = 0; kt < K; kt += BK) {
        // load A tile: As[k][m]
        {
            int m  = tid >> 2;
            int k4 = (tid & 3) << 2;
            float4 av = *(const float4*)(A + (size_t)(m0 + m) * lda + kt + k4);
            As[k4 + 0][m] = av.x; As[k4 + 1][m] = av.y;
            As[k4 + 2][m] = av.z; As[k4 + 3][m] = av.w;
        }
        // load B tile: Bs[k][n]
        if (TRANSB) {
            int n  = tid >> 2;
            int k4 = (tid & 3) << 2;
            float4 bv = *(const float4*)(B + (size_t)(n0 + n) * ldb + kt + k4);
            Bs[k4 + 0][n] = bv.x; Bs[k4 + 1][n] = bv.y;
            Bs[k4 + 2][n] = bv.z; Bs[k4 + 3][n] = bv.w;
        } else {
            int kk = tid >> 4;
            int n4 = (tid & 15) << 2;
            *(float4*)&Bs[kk][n4] =
                *(const float4*)(B + (size_t)(kt + kk) * ldb + n0 + n4);
        }
        __syncthreads();

        #pragma unroll
        for (int k = 0; k < BK; k++) {
            float4 a = *(const float4*)&As[k][ty << 2];
            float4 b = *(const float4*)&Bs[k][tx << 2];
            float av[4] = {a.x, a.y, a.z, a.w};
            float bv[4] = {b.x, b.y, b.z, b.w};
            #pragma unroll
            for (int i = 0; i < 4; i++)
                #pragma unroll
                for (int j = 0; j < 4; j++)
                    acc[i][j] += av[i] * bv[j];
        }
        __syncthreads();
    }

    #pragma unroll
    for (int i = 0; i < 4; i++) {
        int m = m0 + (ty << 2) + i;
        float4 v;
        v.x = acc[i][0] * scale; v.y = acc[i][1] * scale;
        v.z = acc[i][2] * scale; v.w = acc[i][3] * scale;
        if (MASKED) {
            float4 mk = *(const float4*)(Msk + (size_t)m * SEQ + n0 + (tx << 2));
            v.x += mk.x; v.y += mk.y; v.z += mk.z; v.w += mk.w;
        }
        *(float4*)(C + (size_t)m * ldc + n0 + (tx << 2)) = v;
    }
}

// ---------------- RoPE (in place on [SEQ, H*192] at dim offset 128) ----------------
__global__ void rope_kernel(float* __restrict__ X)
{
    int idx = blockIdx.x * blockDim.x + threadIdx.x;   // SEQ*NH*32 threads
    int j = idx & 31;
    int h = (idx >> 5) & (NH - 1);
    int t = idx >> 9;
    float* p = X + (size_t)t * 3072 + h * DQK + 128;
    float inv = powf(10000.0f, -(float)j / 32.0f);
    float ang = (float)t * inv;
    float s, c;
    sincosf(ang, &s, &c);
    float x1 = p[j], x2 = p[j + 32];
    p[j]      = x1 * c - x2 * s;
    p[j + 32] = x2 * c + x1 * s;
}

// ---------------- row softmax over SEQ, per (row, head) ----------------
__global__ __launch_bounds__(256) void softmax_kernel(float* __restrict__ S)
{
    float* row = S + ((size_t)blockIdx.y * SEQ + blockIdx.x) * SEQ;
    const int tid = threadIdx.x;
    __shared__ float red[8];

    float v[8];
    float m = -1e30f;
    #pragma unroll
    for (int i = 0; i < 8; i++) { v[i] = row[tid + (i << 8)]; m = fmaxf(m, v[i]); }
    #pragma unroll
    for (int o = 16; o; o >>= 1) m = fmaxf(m, __shfl_xor_sync(0xffffffffu, m, o));
    if ((tid & 31) == 0) red[tid >> 5] = m;
    __syncthreads();
    m = red[0];
    #pragma unroll
    for (int i = 1; i < 8; i++) m = fmaxf(m, red[i]);

    float s = 0.f;
    #pragma unroll
    for (int i = 0; i < 8; i++) { v[i] = expf(v[i] - m); s += v[i]; }
    #pragma unroll
    for (int o = 16; o; o >>= 1) s += __shfl_xor_sync(0xffffffffu, s, o);
    __syncthreads();
    if ((tid & 31) == 0) red[tid >> 5] = s;
    __syncthreads();
    s = 0.f;
    #pragma unroll
    for (int i = 0; i < 8; i++) s += red[i];
    float inv = 1.0f / s;
    #pragma unroll
    for (int i = 0; i < 8; i++) row[tid + (i << 8)] = v[i] * inv;
}

// ---------------- launch ----------------
extern "C" void kernel_launch(void* const* d_in, const int* in_sizes, int n_in,
                              void* d_out, int out_size)
{
    const float* hs       = (const float*)d_in[0];
    const float* mask     = (const float*)d_in[1];
    const float* Wq_down  = (const float*)d_in[2];
    const float* Wq_up    = (const float*)d_in[3];
    const float* Wkv_down = (const float*)d_in[4];
    const float* Wk_up    = (const float*)d_in[5];
    const float* Wv_up    = (const float*)d_in[6];
    const float* Wo       = (const float*)d_in[7];
    float* out = (float*)d_out;

    float *q1, *q, *ckv, *k, *v, *p, *attn;
    cudaGetSymbolAddress((void**)&q1,   g_q1);
    cudaGetSymbolAddress((void**)&q,    g_q);
    cudaGetSymbolAddress((void**)&ckv,  g_ckv);
    cudaGetSymbolAddress((void**)&k,    g_k);
    cudaGetSymbolAddress((void**)&v,    g_v);
    cudaGetSymbolAddress((void**)&p,    g_p);
    cudaGetSymbolAddress((void**)&attn, g_attn);

    const float scale = 1.0f / sqrtf((float)DQK);

    // q1 = hs @ Wq_down   [2048,2048]x[2048,1536]
    gemm_tile<false, false><<<dim3(1536 / 64, SEQ / 64, 1), 256>>>(
        hs, Wq_down, q1, nullptr, 2048, 2048, 1536, 1536, 0, 0, 0, 1.f);
    // q = q1 @ Wq_up      [2048,1536]x[1536,3072]
    gemm_tile<false, false><<<dim3(3072 / 64, SEQ / 64, 1), 256>>>(
        q1, Wq_up, q, nullptr, 1536, 1536, 3072, 3072, 0, 0, 0, 1.f);
    // ckv = hs @ Wkv_down [2048,2048]x[2048,512]
    gemm_tile<false, false><<<dim3(512 / 64, SEQ / 64, 1), 256>>>(
        hs, Wkv_down, ckv, nullptr, 2048, 2048, 512, 512, 0, 0, 0, 1.f);
    // k = ckv @ Wk_up     [2048,512]x[512,3072]
    gemm_tile<false, false><<<dim3(3072 / 64, SEQ / 64, 1), 256>>>(
        ckv, Wk_up, k, nullptr, 512, 512, 3072, 3072, 0, 0, 0, 1.f);
    // v = ckv @ Wv_up     [2048,512]x[512,2048]
    gemm_tile<false, false><<<dim3(2048 / 64, SEQ / 64, 1), 256>>>(
        ckv, Wv_up, v, nullptr, 512, 512, 2048, 2048, 0, 0, 0, 1.f);

    // RoPE in place on q and k
    rope_kernel<<<(SEQ * NH * 32) / 256, 256>>>(q);
    rope_kernel<<<(SEQ * NH * 32) / 256, 256>>>(k);

    // scores = scale * q @ k^T + mask   (per head, NT)
    gemm_tile<true, true><<<dim3(SEQ / 64, SEQ / 64, NH), 256>>>(
        q, k, p, mask, DQK, 3072, 3072, SEQ,
        (long)DQK, (long)DQK, (long)SEQ * SEQ, scale);

    // softmax rows
    softmax_kernel<<<dim3(SEQ, NH), 256>>>(p);

    // attn = P @ V  (per head, NN) -> [SEQ, H*128]
    gemm_tile<false, false><<<dim3(128 / 64, SEQ / 64, NH), 256>>>(
        p, v, attn, nullptr, SEQ, SEQ, 2048, 2048,
        (long)SEQ * SEQ, 128L, 128L, 1.f);

    // out = attn @ Wo     [2048,2048]x[2048,2048]
    gemm_tile<false, false><<<dim3(2048 / 64, SEQ / 64, 1), 256>>>(
        attn, Wo, out, nullptr, 2048, 2048, 2048, 2048, 0, 0, 0, 1.f);
}

// round 2
// speedup vs baseline: 2.0866x; 2.0866x over previous
#include <cuda_runtime.h>
#include <math.h>

#define SEQ 2048
#define NH 16
#define DQK 192

// ---------------- scratch (no allocations allowed) ----------------
__device__ __align__(16) float g_q1[SEQ * 1536];
__device__ __align__(16) float g_q [SEQ * 3072];
__device__ __align__(16) float g_ckv[SEQ * 512];
__device__ __align__(16) float g_k [SEQ * 3072];
__device__ __align__(16) float g_v [SEQ * 2048];
__device__ __align__(16) float g_p [(size_t)NH * SEQ * SEQ];   // scores / probs
__device__ __align__(16) float g_attn[SEQ * 2048];

// round fp32 -> tf32 (RN), keep as float bit-pattern
__device__ __forceinline__ float tf32r(float x) {
    unsigned u;
    asm("cvt.rna.tf32.f32 %0, %1;" : "=r"(u) : "f"(x));
    return __uint_as_float(u);
}
__device__ __forceinline__ unsigned fb(float x) { return __float_as_uint(x); }

__device__ __forceinline__ void mma_tf32(float* c, const unsigned* a, const unsigned* b) {
    asm volatile(
        "mma.sync.aligned.m16n8k8.row.col.f32.tf32.tf32.f32 "
        "{%0,%1,%2,%3}, {%4,%5,%6,%7}, {%8,%9}, {%0,%1,%2,%3};"
        : "+f"(c[0]), "+f"(c[1]), "+f"(c[2]), "+f"(c[3])
        : "r"(a[0]), "r"(a[1]), "r"(a[2]), "r"(a[3]), "r"(b[0]), "r"(b[1]));
}

// ---------------- tf32 tensor-core GEMM ----------------
// C[m,n] = scale * sum_k A[m,k] * (TRANSB ? B[n,k] : B[k,n])  (+ Msk[m*SEQ+n])
// block tile 128x128, BK=16, 256 threads (8 warps, 2x4 warp grid, 64x32 warp tile)
template <bool TRANSB, bool MASKED>
__global__ __launch_bounds__(256, 2) void gemm_tf32(
    const float* __restrict__ A, const float* __restrict__ B,
    float* __restrict__ C, const float* __restrict__ Msk,
    int K, int lda, int ldb, int ldc,
    long sa, long sb, long sc, float scale)
{
    __shared__ float As[2][16][132];   // [k][m]
    __shared__ float Bs[2][16][132];   // [k][n]

    const int t = threadIdx.x;
    const int m0 = blockIdx.y * 128;
    const int n0 = blockIdx.x * 128;
    A += (size_t)blockIdx.z * sa;
    B += (size_t)blockIdx.z * sb;
    C += (size_t)blockIdx.z * sc;

    // loader indices
    const int am = t >> 1;          // 0..127 (row for A, row n for trans-B)
    const int ak = (t & 1) * 8;     // k sub-offset
    const int bk = t >> 4;          // 0..15 (k row for non-trans B)
    const int bn = (t & 15) * 8;    // n sub-offset

    // warp/frag indices
    const int lane = t & 31;
    const int warp = t >> 5;
    const int wm = (warp >> 2) * 64;
    const int wn = (warp & 3) * 32;
    const int qk = lane & 3;
    const int qr = lane >> 2;

    float acc[4][4][4] = {};
    float4 ra0, ra1, rb0, rb1;

    // ---- initial tile load ----
    {
        const float* pa = A + (size_t)(m0 + am) * lda + ak;
        ra0 = *(const float4*)pa; ra1 = *(const float4*)(pa + 4);
        if (TRANSB) {
            const float* pb = B + (size_t)(n0 + am) * ldb + ak;
            rb0 = *(const float4*)pb; rb1 = *(const float4*)(pb + 4);
        } else {
            const float* pb = B + (size_t)bk * ldb + n0 + bn;
            rb0 = *(const float4*)pb; rb1 = *(const float4*)(pb + 4);
        }
        As[0][ak + 0][am] = tf32r(ra0.x); As[0][ak + 1][am] = tf32r(ra0.y);
        As[0][ak + 2][am] = tf32r(ra0.z); As[0][ak + 3][am] = tf32r(ra0.w);
        As[0][ak + 4][am] = tf32r(ra1.x); As[0][ak + 5][am] = tf32r(ra1.y);
        As[0][ak + 6][am] = tf32r(ra1.z); As[0][ak + 7][am] = tf32r(ra1.w);
        if (TRANSB) {
            Bs[0][ak + 0][am] = tf32r(rb0.x); Bs[0][ak + 1][am] = tf32r(rb0.y);
            Bs[0][ak + 2][am] = tf32r(rb0.z); Bs[0][ak + 3][am] = tf32r(rb0.w);
            Bs[0][ak + 4][am] = tf32r(rb1.x); Bs[0][ak + 5][am] = tf32r(rb1.y);
            Bs[0][ak + 6][am] = tf32r(rb1.z); Bs[0][ak + 7][am] = tf32r(rb1.w);
        } else {
            Bs[0][bk][bn + 0] = tf32r(rb0.x); Bs[0][bk][bn + 1] = tf32r(rb0.y);
            Bs[0][bk][bn + 2] = tf32r(rb0.z); Bs[0][bk][bn + 3] = tf32r(rb0.w);
            Bs[0][bk][bn + 4] = tf32r(rb1.x); Bs[0][bk][bn + 5] = tf32r(rb1.y);
            Bs[0][bk][bn + 6] = tf32r(rb1.z); Bs[0][bk][bn + 7] = tf32r(rb1.w);
        }
    }
    __syncthreads();

    int buf = 0;
    for (int kt = 0; kt < K; kt += 16) {
        const bool more = (kt + 16) < K;
        if (more) {
            const float* pa = A + (size_t)(m0 + am) * lda + kt + 16 + ak;
            ra0 = *(const float4*)pa; ra1 = *(const float4*)(pa + 4);
            if (TRANSB) {
                const float* pb = B + (size_t)(n0 + am) * ldb + kt + 16 + ak;
                rb0 = *(const float4*)pb; rb1 = *(const float4*)(pb + 4);
            } else {
                const float* pb = B + (size_t)(kt + 16 + bk) * ldb + n0 + bn;
                rb0 = *(const float4*)pb; rb1 = *(const float4*)(pb + 4);
            }
        }

        // ---- compute on current buffer ----
        #pragma unroll
        for (int k8 = 0; k8 < 16; k8 += 8) {
            unsigned af[4][4], bf[4][2];
            #pragma unroll
            for (int mi = 0; mi < 4; mi++) {
                const int m = wm + mi * 16 + qr;
                af[mi][0] = fb(As[buf][k8 + qk][m]);
                af[mi][1] = fb(As[buf][k8 + qk][m + 8]);
                af[mi][2] = fb(As[buf][k8 + qk + 4][m]);
                af[mi][3] = fb(As[buf][k8 + qk + 4][m + 8]);
            }
            #pragma unroll
            for (int ni = 0; ni < 4; ni++) {
                const int n = wn + ni * 8 + qr;
                bf[ni][0] = fb(Bs[buf][k8 + qk][n]);
                bf[ni][1] = fb(Bs[buf][k8 + qk + 4][n]);
            }
            #pragma unroll
            for (int mi = 0; mi < 4; mi++)
                #pragma unroll
                for (int ni = 0; ni < 4; ni++)
                    mma_tf32(acc[mi][ni], af[mi], bf[ni]);
        }

        if (more) {
            const int nb = buf ^ 1;
            As[nb][ak + 0][am] = tf32r(ra0.x); As[nb][ak + 1][am] = tf32r(ra0.y);
            As[nb][ak + 2][am] = tf32r(ra0.z); As[nb][ak + 3][am] = tf32r(ra0.w);
            As[nb][ak + 4][am] = tf32r(ra1.x); As[nb][ak + 5][am] = tf32r(ra1.y);
            As[nb][ak + 6][am] = tf32r(ra1.z); As[nb][ak + 7][am] = tf32r(ra1.w);
            if (TRANSB) {
                Bs[nb][ak + 0][am] = tf32r(rb0.x); Bs[nb][ak + 1][am] = tf32r(rb0.y);
                Bs[nb][ak + 2][am] = tf32r(rb0.z); Bs[nb][ak + 3][am] = tf32r(rb0.w);
                Bs[nb][ak + 4][am] = tf32r(rb1.x); Bs[nb][ak + 5][am] = tf32r(rb1.y);
                Bs[nb][ak + 6][am] = tf32r(rb1.z); Bs[nb][ak + 7][am] = tf32r(rb1.w);
            } else {
                Bs[nb][bk][bn + 0] = tf32r(rb0.x); Bs[nb][bk][bn + 1] = tf32r(rb0.y);
                Bs[nb][bk][bn + 2] = tf32r(rb0.z); Bs[nb][bk][bn + 3] = tf32r(rb0.w);
                Bs[nb][bk][bn + 4] = tf32r(rb1.x); Bs[nb][bk][bn + 5] = tf32r(rb1.y);
                Bs[nb][bk][bn + 6] = tf32r(rb1.z); Bs[nb][bk][bn + 7] = tf32r(rb1.w);
            }
            __syncthreads();
            buf ^= 1;
        }
    }

    // ---- epilogue ----
    #pragma unroll
    for (int mi = 0; mi < 4; mi++) {
        #pragma unroll
        for (int ni = 0; ni < 4; ni++) {
            const int m = m0 + wm + mi * 16 + qr;
            const int n = n0 + wn + ni * 8 + 2 * qk;
            float2 v0, v1;
            v0.x = acc[mi][ni][0] * scale; v0.y = acc[mi][ni][1] * scale;
            v1.x = acc[mi][ni][2] * scale; v1.y = acc[mi][ni][3] * scale;
            if (MASKED) {
                float2 mk0 = *(const float2*)(Msk + (size_t)m * SEQ + n);
                float2 mk1 = *(const float2*)(Msk + (size_t)(m + 8) * SEQ + n);
                v0.x += mk0.x; v0.y += mk0.y;
                v1.x += mk1.x; v1.y += mk1.y;
            }
            *(float2*)(C + (size_t)m * ldc + n)       = v0;
            *(float2*)(C + (size_t)(m + 8) * ldc + n) = v1;
        }
    }
}

// ---------------- RoPE (in place on [SEQ, H*192] at dim offset 128) ----------------
__global__ void rope_kernel(float* __restrict__ X)
{
    int idx = blockIdx.x * blockDim.x + threadIdx.x;   // SEQ*NH*32 threads
    int j = idx & 31;
    int h = (idx >> 5) & (NH - 1);
    int t = idx >> 9;
    float* p = X + (size_t)t * 3072 + h * DQK + 128;
    float inv = powf(10000.0f, -(float)j / 32.0f);
    float ang = (float)t * inv;
    float s, c;
    sincosf(ang, &s, &c);
    float x1 = p[j], x2 = p[j + 32];
    p[j]      = x1 * c - x2 * s;
    p[j + 32] = x2 * c + x1 * s;
}

// ---------------- row softmax over SEQ, per (row, head) ----------------
__global__ __launch_bounds__(256) void softmax_kernel(float* __restrict__ S)
{
    float* row = S + ((size_t)blockIdx.y * SEQ + blockIdx.x) * SEQ;
    const int tid = threadIdx.x;
    __shared__ float red[8];

    float v[8];
    float m = -1e30f;
    #pragma unroll
    for (int i = 0; i < 8; i++) { v[i] = row[tid + (i << 8)]; m = fmaxf(m, v[i]); }
    #pragma unroll
    for (int o = 16; o; o >>= 1) m = fmaxf(m, __shfl_xor_sync(0xffffffffu, m, o));
    if ((tid & 31) == 0) red[tid >> 5] = m;
    __syncthreads();
    m = red[0];
    #pragma unroll
    for (int i = 1; i < 8; i++) m = fmaxf(m, red[i]);

    float s = 0.f;
    #pragma unroll
    for (int i = 0; i < 8; i++) { v[i] = expf(v[i] - m); s += v[i]; }
    #pragma unroll
    for (int o = 16; o; o >>= 1) s += __shfl_xor_sync(0xffffffffu, s, o);
    __syncthreads();
    if ((tid & 31) == 0) red[tid >> 5] = s;
    __syncthreads();
    s = 0.f;
    #pragma unroll
    for (int i = 0; i < 8; i++) s += red[i];
    float inv = 1.0f / s;
    #pragma unroll
    for (int i = 0; i < 8; i++) row[tid + (i << 8)] = v[i] * inv;
}

// ---------------- launch ----------------
extern "C" void kernel_launch(void* const* d_in, const int* in_sizes, int n_in,
                              void* d_out, int out_size)
{
    const float* hs       = (const float*)d_in[0];
    const float* mask     = (const float*)d_in[1];
    const float* Wq_down  = (const float*)d_in[2];
    const float* Wq_up    = (const float*)d_in[3];
    const float* Wkv_down = (const float*)d_in[4];
    const float* Wk_up    = (const float*)d_in[5];
    const float* Wv_up    = (const float*)d_in[6];
    const float* Wo       = (const float*)d_in[7];
    float* out = (float*)d_out;

    float *q1, *q, *ckv, *k, *v, *p, *attn;
    cudaGetSymbolAddress((void**)&q1,   g_q1);
    cudaGetSymbolAddress((void**)&q,    g_q);
    cudaGetSymbolAddress((void**)&ckv,  g_ckv);
    cudaGetSymbolAddress((void**)&k,    g_k);
    cudaGetSymbolAddress((void**)&v,    g_v);
    cudaGetSymbolAddress((void**)&p,    g_p);
    cudaGetSymbolAddress((void**)&attn, g_attn);

    const float scale = 1.0f / sqrtf((float)DQK);

    // q1 = hs @ Wq_down   [2048,2048]x[2048,1536]
    gemm_tf32<false, false><<<dim3(1536 / 128, SEQ / 128, 1), 256>>>(
        hs, Wq_down, q1, nullptr, 2048, 2048, 1536, 1536, 0, 0, 0, 1.f);
    // q = q1 @ Wq_up      [2048,1536]x[1536,3072]
    gemm_tf32<false, false><<<dim3(3072 / 128, SEQ / 128, 1), 256>>>(
        q1, Wq_up, q, nullptr, 1536, 1536, 3072, 3072, 0, 0, 0, 1.f);
    // ckv = hs @ Wkv_down [2048,2048]x[2048,512]
    gemm_tf32<false, false><<<dim3(512 / 128, SEQ / 128, 1), 256>>>(
        hs, Wkv_down, ckv, nullptr, 2048, 2048, 512, 512, 0, 0, 0, 1.f);
    // k = ckv @ Wk_up     [2048,512]x[512,3072]
    gemm_tf32<false, false><<<dim3(3072 / 128, SEQ / 128, 1), 256>>>(
        ckv, Wk_up, k, nullptr, 512, 512, 3072, 3072, 0, 0, 0, 1.f);
    // v = ckv @ Wv_up     [2048,512]x[512,2048]
    gemm_tf32<false, false><<<dim3(2048 / 128, SEQ / 128, 1), 256>>>(
        ckv, Wv_up, v, nullptr, 512, 512, 2048, 2048, 0, 0, 0, 1.f);

    // RoPE in place on q and k
    rope_kernel<<<(SEQ * NH * 32) / 256, 256>>>(q);
    rope_kernel<<<(SEQ * NH * 32) / 256, 256>>>(k);

    // scores = scale * q @ k^T + mask   (per head, NT)
    gemm_tf32<true, true><<<dim3(SEQ / 128, SEQ / 128, NH), 256>>>(
        q, k, p, mask, DQK, 3072, 3072, SEQ,
        (long)DQK, (long)DQK, (long)SEQ * SEQ, scale);

    // softmax rows
    softmax_kernel<<<dim3(SEQ, NH), 256>>>(p);

    // attn = P @ V  (per head, NN) -> [SEQ, H*128]
    gemm_tf32<false, false><<<dim3(128 / 128, SEQ / 128, NH), 256>>>(
        p, v, attn, nullptr, SEQ, SEQ, 2048, 2048,
        (long)SEQ * SEQ, 128L, 128L, 1.f);

    // out = attn @ Wo     [2048,2048]x[2048,2048]
    gemm_tf32<false, false><<<dim3(2048 / 128, SEQ / 128, 1), 256>>>(
        attn, Wo, out, nullptr, 2048, 2048, 2048, 2048, 0, 0, 0, 1.f);
}

// round 3
// speedup vs baseline: 2.9006x; 1.3901x over previous
#include <cuda_runtime.h>
#include <math.h>

#define SEQ 2048
#define NH 16
#define DQK 192

// ---------------- scratch (no allocations allowed) ----------------
__device__ __align__(16) float g_q1[SEQ * 1536];
__device__ __align__(16) float g_q [SEQ * 3072];
__device__ __align__(16) float g_ckv[SEQ * 512];
__device__ __align__(16) float g_k [SEQ * 3072];
__device__ __align__(16) float g_v [SEQ * 2048];
__device__ __align__(16) float g_attn[SEQ * 2048];

// round fp32 -> tf32 (RN), keep as float bit-pattern
__device__ __forceinline__ float tf32r(float x) {
    unsigned u;
    asm("cvt.rna.tf32.f32 %0, %1;" : "=r"(u) : "f"(x));
    return __uint_as_float(u);
}
__device__ __forceinline__ unsigned fb(float x) { return __float_as_uint(x); }

__device__ __forceinline__ void mma_tf32(float* c, const unsigned* a, const unsigned* b) {
    asm volatile(
        "mma.sync.aligned.m16n8k8.row.col.f32.tf32.tf32.f32 "
        "{%0,%1,%2,%3}, {%4,%5,%6,%7}, {%8,%9}, {%0,%1,%2,%3};"
        : "+f"(c[0]), "+f"(c[1]), "+f"(c[2]), "+f"(c[3])
        : "r"(a[0]), "r"(a[1]), "r"(a[2]), "r"(a[3]), "r"(b[0]), "r"(b[1]));
}

// ---------------- tf32 tensor-core GEMM (projections) ----------------
// C[m,n] = sum_k A[m,k] * B[k,n]
template <bool TRANSB, bool MASKED>
__global__ __launch_bounds__(256, 2) void gemm_tf32(
    const float* __restrict__ A, const float* __restrict__ B,
    float* __restrict__ C, const float* __restrict__ Msk,
    int K, int lda, int ldb, int ldc,
    long sa, long sb, long sc, float scale)
{
    __shared__ float As[2][16][132];   // [k][m]
    __shared__ float Bs[2][16][132];   // [k][n]

    const int t = threadIdx.x;
    const int m0 = blockIdx.y * 128;
    const int n0 = blockIdx.x * 128;
    A += (size_t)blockIdx.z * sa;
    B += (size_t)blockIdx.z * sb;
    C += (size_t)blockIdx.z * sc;

    const int am = t >> 1;
    const int ak = (t & 1) * 8;
    const int bk = t >> 4;
    const int bn = (t & 15) * 8;

    const int lane = t & 31;
    const int warp = t >> 5;
    const int wm = (warp >> 2) * 64;
    const int wn = (warp & 3) * 32;
    const int qk = lane & 3;
    const int qr = lane >> 2;

    float acc[4][4][4] = {};
    float4 ra0, ra1, rb0, rb1;

    {
        const float* pa = A + (size_t)(m0 + am) * lda + ak;
        ra0 = *(const float4*)pa; ra1 = *(const float4*)(pa + 4);
        if (TRANSB) {
            const float* pb = B + (size_t)(n0 + am) * ldb + ak;
            rb0 = *(const float4*)pb; rb1 = *(const float4*)(pb + 4);
        } else {
            const float* pb = B + (size_t)bk * ldb + n0 + bn;
            rb0 = *(const float4*)pb; rb1 = *(const float4*)(pb + 4);
        }
        As[0][ak + 0][am] = tf32r(ra0.x); As[0][ak + 1][am] = tf32r(ra0.y);
        As[0][ak + 2][am] = tf32r(ra0.z); As[0][ak + 3][am] = tf32r(ra0.w);
        As[0][ak + 4][am] = tf32r(ra1.x); As[0][ak + 5][am] = tf32r(ra1.y);
        As[0][ak + 6][am] = tf32r(ra1.z); As[0][ak + 7][am] = tf32r(ra1.w);
        if (TRANSB) {
            Bs[0][ak + 0][am] = tf32r(rb0.x); Bs[0][ak + 1][am] = tf32r(rb0.y);
            Bs[0][ak + 2][am] = tf32r(rb0.z); Bs[0][ak + 3][am] = tf32r(rb0.w);
            Bs[0][ak + 4][am] = tf32r(rb1.x); Bs[0][ak + 5][am] = tf32r(rb1.y);
            Bs[0][ak + 6][am] = tf32r(rb1.z); Bs[0][ak + 7][am] = tf32r(rb1.w);
        } else {
            Bs[0][bk][bn + 0] = tf32r(rb0.x); Bs[0][bk][bn + 1] = tf32r(rb0.y);
            Bs[0][bk][bn + 2] = tf32r(rb0.z); Bs[0][bk][bn + 3] = tf32r(rb0.w);
            Bs[0][bk][bn + 4] = tf32r(rb1.x); Bs[0][bk][bn + 5] = tf32r(rb1.y);
            Bs[0][bk][bn + 6] = tf32r(rb1.z); Bs[0][bk][bn + 7] = tf32r(rb1.w);
        }
    }
    __syncthreads();

    int buf = 0;
    for (int kt = 0; kt < K; kt += 16) {
        const bool more = (kt + 16) < K;
        if (more) {
            const float* pa = A + (size_t)(m0 + am) * lda + kt + 16 + ak;
            ra0 = *(const float4*)pa; ra1 = *(const float4*)(pa + 4);
            if (TRANSB) {
                const float* pb = B + (size_t)(n0 + am) * ldb + kt + 16 + ak;
                rb0 = *(const float4*)pb; rb1 = *(const float4*)(pb + 4);
            } else {
                const float* pb = B + (size_t)(kt + 16 + bk) * ldb + n0 + bn;
                rb0 = *(const float4*)pb; rb1 = *(const float4*)(pb + 4);
            }
        }

        #pragma unroll
        for (int k8 = 0; k8 < 16; k8 += 8) {
            unsigned af[4][4], bfr[4][2];
            #pragma unroll
            for (int mi = 0; mi < 4; mi++) {
                const int m = wm + mi * 16 + qr;
                af[mi][0] = fb(As[buf][k8 + qk][m]);
                af[mi][1] = fb(As[buf][k8 + qk][m + 8]);
                af[mi][2] = fb(As[buf][k8 + qk + 4][m]);
                af[mi][3] = fb(As[buf][k8 + qk + 4][m + 8]);
            }
            #pragma unroll
            for (int ni = 0; ni < 4; ni++) {
                const int n = wn + ni * 8 + qr;
                bfr[ni][0] = fb(Bs[buf][k8 + qk][n]);
                bfr[ni][1] = fb(Bs[buf][k8 + qk + 4][n]);
            }
            #pragma unroll
            for (int mi = 0; mi < 4; mi++)
                #pragma unroll
                for (int ni = 0; ni < 4; ni++)
                    mma_tf32(acc[mi][ni], af[mi], bfr[ni]);
        }

        if (more) {
            const int nb = buf ^ 1;
            As[nb][ak + 0][am] = tf32r(ra0.x); As[nb][ak + 1][am] = tf32r(ra0.y);
            As[nb][ak + 2][am] = tf32r(ra0.z); As[nb][ak + 3][am] = tf32r(ra0.w);
            As[nb][ak + 4][am] = tf32r(ra1.x); As[nb][ak + 5][am] = tf32r(ra1.y);
            As[nb][ak + 6][am] = tf32r(ra1.z); As[nb][ak + 7][am] = tf32r(ra1.w);
            if (TRANSB) {
                Bs[nb][ak + 0][am] = tf32r(rb0.x); Bs[nb][ak + 1][am] = tf32r(rb0.y);
                Bs[nb][ak + 2][am] = tf32r(rb0.z); Bs[nb][ak + 3][am] = tf32r(rb0.w);
                Bs[nb][ak + 4][am] = tf32r(rb1.x); Bs[nb][ak + 5][am] = tf32r(rb1.y);
                Bs[nb][ak + 6][am] = tf32r(rb1.z); Bs[nb][ak + 7][am] = tf32r(rb1.w);
            } else {
                Bs[nb][bk][bn + 0] = tf32r(rb0.x); Bs[nb][bk][bn + 1] = tf32r(rb0.y);
                Bs[nb][bk][bn + 2] = tf32r(rb0.z); Bs[nb][bk][bn + 3] = tf32r(rb0.w);
                Bs[nb][bk][bn + 4] = tf32r(rb1.x); Bs[nb][bk][bn + 5] = tf32r(rb1.y);
                Bs[nb][bk][bn + 6] = tf32r(rb1.z); Bs[nb][bk][bn + 7] = tf32r(rb1.w);
            }
            __syncthreads();
            buf ^= 1;
        }
    }

    #pragma unroll
    for (int mi = 0; mi < 4; mi++) {
        #pragma unroll
        for (int ni = 0; ni < 4; ni++) {
            const int m = m0 + wm + mi * 16 + qr;
            const int n = n0 + wn + ni * 8 + 2 * qk;
            float2 v0, v1;
            v0.x = acc[mi][ni][0] * scale; v0.y = acc[mi][ni][1] * scale;
            v1.x = acc[mi][ni][2] * scale; v1.y = acc[mi][ni][3] * scale;
            *(float2*)(C + (size_t)m * ldc + n)       = v0;
            *(float2*)(C + (size_t)(m + 8) * ldc + n) = v1;
        }
    }
}

// ---------------- RoPE (in place on [SEQ, H*192] at dim offset 128) ----------------
__global__ void rope_kernel(float* __restrict__ X)
{
    int idx = blockIdx.x * blockDim.x + threadIdx.x;
    int j = idx & 31;
    int h = (idx >> 5) & (NH - 1);
    int t = idx >> 9;
    float* p = X + (size_t)t * 3072 + h * DQK + 128;
    float inv = powf(10000.0f, -(float)j / 32.0f);
    float ang = (float)t * inv;
    float s, c;
    sincosf(ang, &s, &c);
    float x1 = p[j], x2 = p[j + 32];
    p[j]      = x1 * c - x2 * s;
    p[j + 32] = x2 * c + x1 * s;
}

// ---------------- fused causal flash attention ----------------
// Per CTA: one head, 128 Q rows. Loops over 64-row K/V tiles up to diagonal.
// 8 warps; warp w owns S rows [16w,16w+16) x 64 cols, O rows [16w,16w+16) x 128.
#define LDQ 196
#define LDK 196
#define LDV 136
#define LDP 68
#define FLASH_SMEM ((128*LDQ + 64*LDK + 64*LDV + 128*LDP) * 4)

__global__ __launch_bounds__(256, 1) void flash_attn(
    const float* __restrict__ Qg, const float* __restrict__ Kg,
    const float* __restrict__ Vg, float* __restrict__ Og)
{
    extern __shared__ float sm[];
    float* Qs = sm;                       // [128][196]
    float* Ks = Qs + 128 * LDQ;           // [64][196]
    float* Vs = Ks + 64 * LDK;            // [64][136]  ([k][n])
    float* Ps = Vs + 64 * LDV;            // [128][68]

    const int h   = blockIdx.x;
    const int qt  = 15 - blockIdx.y;      // long CTAs first
    const int tid = threadIdx.x;
    const int lane = tid & 31;
    const int warp = tid >> 5;
    const int qr = lane >> 2;
    const int qk = lane & 3;
    const int wm = warp * 16;

    const float cs = 0.10411758f;         // log2(e)/sqrt(192)

    // ---- load Q tile [128 x 192] (coalesced 128B per 8-thread group) ----
    {
        const int rr = tid >> 3;          // 0..31
        const int cc = (tid & 7) * 4;     // 0..28
        #pragma unroll
        for (int rb = 0; rb < 4; rb++) {
            const int r = rb * 32 + rr;
            const float* src = Qg + (size_t)(qt * 128 + r) * 3072 + h * DQK;
            float* dst = Qs + r * LDQ;
            #pragma unroll
            for (int ch = 0; ch < 6; ch++) {
                float4 v4 = *(const float4*)(src + ch * 32 + cc);
                float* d = dst + ch * 32 + cc;
                d[0] = tf32r(v4.x); d[1] = tf32r(v4.y);
                d[2] = tf32r(v4.z); d[3] = tf32r(v4.w);
            }
        }
    }

    float o[16][4];
    #pragma unroll
    for (int i = 0; i < 16; i++)
        #pragma unroll
        for (int j = 0; j < 4; j++) o[i][j] = 0.f;
    float m0 = -1e30f, m1 = -1e30f, l0 = 0.f, l1 = 0.f;

    const int njt = 2 * qt + 2;
    for (int jt = 0; jt < njt; jt++) {
        __syncthreads();   // previous iteration's readers of Ks/Vs done
        // ---- load K tile [64 x 192] ----
        {
            const int rr = tid >> 3;
            const int cc = (tid & 7) * 4;
            #pragma unroll
            for (int rb = 0; rb < 2; rb++) {
                const int r = rb * 32 + rr;
                const float* src = Kg + (size_t)(jt * 64 + r) * 3072 + h * DQK;
                float* dst = Ks + r * LDK;
                #pragma unroll
                for (int ch = 0; ch < 6; ch++) {
                    float4 v4 = *(const float4*)(src + ch * 32 + cc);
                    float* d = dst + ch * 32 + cc;
                    d[0] = tf32r(v4.x); d[1] = tf32r(v4.y);
                    d[2] = tf32r(v4.z); d[3] = tf32r(v4.w);
                }
            }
        }
        // ---- load V tile [64 x 128] ----
        {
            const int rr = tid >> 3;
            const int cc = (tid & 7) * 4;
            #pragma unroll
            for (int rb = 0; rb < 2; rb++) {
                const int r = rb * 32 + rr;
                const float* src = Vg + (size_t)(jt * 64 + r) * 2048 + h * 128;
                float* dst = Vs + r * LDV;
                #pragma unroll
                for (int ch = 0; ch < 4; ch++) {
                    float4 v4 = *(const float4*)(src + ch * 32 + cc);
                    float* d = dst + ch * 32 + cc;
                    d[0] = tf32r(v4.x); d[1] = tf32r(v4.y);
                    d[2] = tf32r(v4.z); d[3] = tf32r(v4.w);
                }
            }
        }
        __syncthreads();

        // ---- S = Q K^T : warp rows [wm, wm+16), cols [0,64) ----
        float s[8][4];
        #pragma unroll
        for (int i = 0; i < 8; i++)
            #pragma unroll
            for (int j = 0; j < 4; j++) s[i][j] = 0.f;

        #pragma unroll
        for (int k8 = 0; k8 < DQK; k8 += 8) {
            unsigned a[4];
            a[0] = fb(Qs[(wm + qr) * LDQ + k8 + qk]);
            a[1] = fb(Qs[(wm + qr + 8) * LDQ + k8 + qk]);
            a[2] = fb(Qs[(wm + qr) * LDQ + k8 + qk + 4]);
            a[3] = fb(Qs[(wm + qr + 8) * LDQ + k8 + qk + 4]);
            #pragma unroll
            for (int nf = 0; nf < 8; nf++) {
                unsigned b[2];
                b[0] = fb(Ks[(nf * 8 + qr) * LDK + k8 + qk]);
                b[1] = fb(Ks[(nf * 8 + qr) * LDK + k8 + qk + 4]);
                mma_tf32(s[nf], a, b);
            }
        }

        // ---- causal mask (only last two tiles can cross the diagonal) ----
        const int rg0 = qt * 128 + wm + qr;
        if (jt >= 2 * qt) {
            #pragma unroll
            for (int nf = 0; nf < 8; nf++) {
                const int cg = jt * 64 + nf * 8 + 2 * qk;
                if (cg     > rg0)     s[nf][0] = -1e30f;
                if (cg + 1 > rg0)     s[nf][1] = -1e30f;
                if (cg     > rg0 + 8) s[nf][2] = -1e30f;
                if (cg + 1 > rg0 + 8) s[nf][3] = -1e30f;
            }
        }

        // ---- online softmax (rows qr and qr+8; quad = 4 lanes per row) ----
        float mx0 = -1e30f, mx1 = -1e30f;
        #pragma unroll
        for (int nf = 0; nf < 8; nf++) {
            mx0 = fmaxf(mx0, fmaxf(s[nf][0], s[nf][1]));
            mx1 = fmaxf(mx1, fmaxf(s[nf][2], s[nf][3]));
        }
        mx0 = fmaxf(mx0, __shfl_xor_sync(0xffffffffu, mx0, 1));
        mx0 = fmaxf(mx0, __shfl_xor_sync(0xffffffffu, mx0, 2));
        mx1 = fmaxf(mx1, __shfl_xor_sync(0xffffffffu, mx1, 1));
        mx1 = fmaxf(mx1, __shfl_xor_sync(0xffffffffu, mx1, 2));

        const float mn0 = fmaxf(m0, mx0);
        const float mn1 = fmaxf(m1, mx1);
        const float al0 = exp2f((m0 - mn0) * cs);
        const float al1 = exp2f((m1 - mn1) * cs);
        m0 = mn0; m1 = mn1;

        float rs0 = 0.f, rs1 = 0.f;
        #pragma unroll
        for (int nf = 0; nf < 8; nf++) {
            s[nf][0] = exp2f((s[nf][0] - mn0) * cs);
            s[nf][1] = exp2f((s[nf][1] - mn0) * cs);
            s[nf][2] = exp2f((s[nf][2] - mn1) * cs);
            s[nf][3] = exp2f((s[nf][3] - mn1) * cs);
            rs0 += s[nf][0] + s[nf][1];
            rs1 += s[nf][2] + s[nf][3];
        }
        rs0 += __shfl_xor_sync(0xffffffffu, rs0, 1);
        rs0 += __shfl_xor_sync(0xffffffffu, rs0, 2);
        rs1 += __shfl_xor_sync(0xffffffffu, rs1, 1);
        rs1 += __shfl_xor_sync(0xffffffffu, rs1, 2);
        l0 = l0 * al0 + rs0;
        l1 = l1 * al1 + rs1;

        // rescale O accumulators
        #pragma unroll
        for (int nf = 0; nf < 16; nf++) {
            o[nf][0] *= al0; o[nf][1] *= al0;
            o[nf][2] *= al1; o[nf][3] *= al1;
        }

        // ---- write P (warp-private rows) then PV ----
        {
            float* p0 = Ps + (wm + qr) * LDP;
            float* p1 = Ps + (wm + qr + 8) * LDP;
            #pragma unroll
            for (int nf = 0; nf < 8; nf++) {
                const int c = nf * 8 + 2 * qk;
                p0[c]     = tf32r(s[nf][0]);
                p0[c + 1] = tf32r(s[nf][1]);
                p1[c]     = tf32r(s[nf][2]);
                p1[c + 1] = tf32r(s[nf][3]);
            }
        }
        __syncwarp();

        #pragma unroll
        for (int k8 = 0; k8 < 64; k8 += 8) {
            unsigned a[4];
            a[0] = fb(Ps[(wm + qr) * LDP + k8 + qk]);
            a[1] = fb(Ps[(wm + qr + 8) * LDP + k8 + qk]);
            a[2] = fb(Ps[(wm + qr) * LDP + k8 + qk + 4]);
            a[3] = fb(Ps[(wm + qr + 8) * LDP + k8 + qk + 4]);
            #pragma unroll
            for (int nf = 0; nf < 16; nf++) {
                unsigned b[2];
                b[0] = fb(Vs[(k8 + qk) * LDV + nf * 8 + qr]);
                b[1] = fb(Vs[(k8 + qk + 4) * LDV + nf * 8 + qr]);
                mma_tf32(o[nf], a, b);
            }
        }
    }

    // ---- epilogue: normalize and store ----
    const float il0 = 1.f / l0;
    const float il1 = 1.f / l1;
    const int rg0 = qt * 128 + wm + qr;
    #pragma unroll
    for (int nf = 0; nf < 16; nf++) {
        const int c = h * 128 + nf * 8 + 2 * qk;
        float2 v0 = make_float2(o[nf][0] * il0, o[nf][1] * il0);
        float2 v1 = make_float2(o[nf][2] * il1, o[nf][3] * il1);
        *(float2*)(Og + (size_t)rg0 * 2048 + c)       = v0;
        *(float2*)(Og + (size_t)(rg0 + 8) * 2048 + c) = v1;
    }
}

// ---------------- launch ----------------
extern "C" void kernel_launch(void* const* d_in, const int* in_sizes, int n_in,
                              void* d_out, int out_size)
{
    const float* hs       = (const float*)d_in[0];
    const float* Wq_down  = (const float*)d_in[2];
    const float* Wq_up    = (const float*)d_in[3];
    const float* Wkv_down = (const float*)d_in[4];
    const float* Wk_up    = (const float*)d_in[5];
    const float* Wv_up    = (const float*)d_in[6];
    const float* Wo       = (const float*)d_in[7];
    float* out = (float*)d_out;

    float *q1, *q, *ckv, *k, *v, *attn;
    cudaGetSymbolAddress((void**)&q1,   g_q1);
    cudaGetSymbolAddress((void**)&q,    g_q);
    cudaGetSymbolAddress((void**)&ckv,  g_ckv);
    cudaGetSymbolAddress((void**)&k,    g_k);
    cudaGetSymbolAddress((void**)&v,    g_v);
    cudaGetSymbolAddress((void**)&attn, g_attn);

    static bool attr_set = false;
    if (!attr_set) {
        cudaFuncSetAttribute(flash_attn,
                             cudaFuncAttributeMaxDynamicSharedMemorySize,
                             FLASH_SMEM);
        attr_set = true;
    }

    // q1 = hs @ Wq_down
    gemm_tf32<false, false><<<dim3(1536 / 128, SEQ / 128, 1), 256>>>(
        hs, Wq_down, q1, nullptr, 2048, 2048, 1536, 1536, 0, 0, 0, 1.f);
    // q = q1 @ Wq_up
    gemm_tf32<false, false><<<dim3(3072 / 128, SEQ / 128, 1), 256>>>(
        q1, Wq_up, q, nullptr, 1536, 1536, 3072, 3072, 0, 0, 0, 1.f);
    // ckv = hs @ Wkv_down
    gemm_tf32<false, false><<<dim3(512 / 128, SEQ / 128, 1), 256>>>(
        hs, Wkv_down, ckv, nullptr, 2048, 2048, 512, 512, 0, 0, 0, 1.f);
    // k = ckv @ Wk_up
    gemm_tf32<false, false><<<dim3(3072 / 128, SEQ / 128, 1), 256>>>(
        ckv, Wk_up, k, nullptr, 512, 512, 3072, 3072, 0, 0, 0, 1.f);
    // v = ckv @ Wv_up
    gemm_tf32<false, false><<<dim3(2048 / 128, SEQ / 128, 1), 256>>>(
        ckv, Wv_up, v, nullptr, 512, 512, 2048, 2048, 0, 0, 0, 1.f);

    // RoPE in place on q and k
    rope_kernel<<<(SEQ * NH * 32) / 256, 256>>>(q);
    rope_kernel<<<(SEQ * NH * 32) / 256, 256>>>(k);

    // fused causal attention -> attn [SEQ, H*128]
    flash_attn<<<dim3(NH, SEQ / 128), 256, FLASH_SMEM>>>(q, k, v, attn);

    // out = attn @ Wo
    gemm_tf32<false, false><<<dim3(2048 / 128, SEQ / 128, 1), 256>>>(
        attn, Wo, out, nullptr, 2048, 2048, 2048, 2048, 0, 0, 0, 1.f);
}